// round 4
// baseline (speedup 1.0000x reference)
#include <cuda_runtime.h>
#include <math.h>

#define T 8192
#define D 4096
#define E 8
#define KSEL 2
#define SLOTS (T * KSEL)
#define NHB 64          // hist blocks
#define SPB (SLOTS / NHB)  // 256 slots per hist block

// Output layout (float32, concatenated in reference-return order)
#define OFF_XG  0
#define OFF_CNT 67108864ll   // 16384*4096
#define OFF_IDX 67108872ll
#define OFF_SC  67125256ll

// Scratch (no allocations allowed -> __device__ globals)
__device__ int   g_exp[SLOTS];
__device__ float g_prob[SLOTS];
__device__ int   g_pos[SLOTS];
__device__ int   g_bhist[NHB * E];

// ---------------------------------------------------------------------------
// Kernel A: router scores + top-2 + softmax.
// Lane-per-(token,expert): warp covers 4 tokens x 8 experts. Each lane
// accumulates its full dot product in-thread over D -> NO reduction shuffles.
// Per 4-dim iter: 2 LDG.128 (x broadcast x8, W broadcast x4) + 4 FFMA/lane.
// grid = T/32 warps -> 256 blocks of 256 threads.
// ---------------------------------------------------------------------------
__global__ void __launch_bounds__(256) router_scores_kernel(
    const float* __restrict__ x, const float* __restrict__ W)
{
    const int warp = blockIdx.x * (blockDim.x >> 5) + (threadIdx.x >> 5);
    const int lane = threadIdx.x & 31;
    const int j    = lane >> 3;     // token within warp's group of 4
    const int e    = lane & 7;      // expert
    const int t0   = warp * 4;

    const float4* __restrict__ xp = (const float4*)(x + (size_t)(t0 + j) * D);
    const float4* __restrict__ wp = (const float4*)(W + (size_t)e * D);

    float ax = 0.f, ay = 0.f, az = 0.f, aw = 0.f;
#pragma unroll 8
    for (int i = 0; i < D / 4; i++) {
        float4 xv = xp[i];
        float4 wv = wp[i];
        ax += xv.x * wv.x;
        ay += xv.y * wv.y;
        az += xv.z * wv.z;
        aw += xv.w * wv.w;
    }
    float s = (ax + ay) + (az + aw);

    // gather the 8 expert scores of this lane's token group
    const int gbase = lane & 24;    // j * 8
    float sv[E];
#pragma unroll
    for (int ee = 0; ee < E; ee++)
        sv[ee] = __shfl_sync(0xffffffffu, s, gbase + ee);

    if (e == 0) {
        const int t = t0 + j;
        // stable top-2 (first occurrence wins ties, matching jax.lax.top_k)
        float b0 = -3.4e38f, b1 = -3.4e38f;
        int i0 = 0, i1 = 0;
#pragma unroll
        for (int ee = 0; ee < E; ee++) {
            float v = sv[ee];
            if (v > b0) { b1 = b0; i1 = i0; b0 = v; i0 = ee; }
            else if (v > b1) { b1 = v; i1 = ee; }
        }
        float ex = expf(b1 - b0);
        float inv = 1.f / (1.f + ex);
        ((int2*)g_exp)[t]   = make_int2(i0, i1);
        ((float2*)g_prob)[t] = make_float2(inv, ex * inv);
    }
}

// ---------------------------------------------------------------------------
// Packed per-expert counters: 8 experts x 8-bit fields across two uints.
// Max count per 256-slot block is 128 (top-2 experts are distinct) -> no
// field overflow.
// ---------------------------------------------------------------------------
__device__ __forceinline__ void packAdd(int e, unsigned& lo, unsigned& hi) {
    if (e < 4) lo += 1u << (8 * e);
    else       hi += 1u << (8 * (e - 4));
}
__device__ __forceinline__ int fieldOf(unsigned lo, unsigned hi, int e) {
    unsigned v = (e < 4) ? lo : hi;
    return (int)((v >> (8 * (e & 3))) & 0xffu);
}

// ---------------------------------------------------------------------------
// Kernel B1: per-block histogram + stable local rank (64 blocks x 256).
// Warp shuffle scan on packed counters; local rank stashed in g_pos.
// ---------------------------------------------------------------------------
__global__ void __launch_bounds__(SPB) rank_hist_kernel()
{
    __shared__ unsigned wlo[8], whi[8];
    const int tid  = threadIdx.x;
    const int wid  = tid >> 5;
    const int lane = tid & 31;
    const int slot = blockIdx.x * SPB + tid;

    const int e = g_exp[slot];
    unsigned lo = 0, hi = 0;
    packAdd(e, lo, hi);
    const unsigned mlo = lo, mhi = hi;

#pragma unroll
    for (int off = 1; off < 32; off <<= 1) {
        unsigned vlo = __shfl_up_sync(0xffffffffu, lo, off);
        unsigned vhi = __shfl_up_sync(0xffffffffu, hi, off);
        if (lane >= off) { lo += vlo; hi += vhi; }
    }
    if (lane == 31) { wlo[wid] = lo; whi[wid] = hi; }
    __syncthreads();

    unsigned plo = 0, phi = 0;
#pragma unroll
    for (int w2 = 0; w2 < 8; w2++)
        if (w2 < wid) { plo += wlo[w2]; phi += whi[w2]; }

    const unsigned exlo = plo + lo - mlo;
    const unsigned exhi = phi + hi - mhi;
    g_pos[slot] = fieldOf(exlo, exhi, e);   // local stable rank within block

    if (tid < E) {
        unsigned tlo = 0, thi = 0;
#pragma unroll
        for (int w2 = 0; w2 < 8; w2++) { tlo += wlo[w2]; thi += whi[w2]; }
        g_bhist[blockIdx.x * E + tid] = fieldOf(tlo, thi, tid);
    }
}

// ---------------------------------------------------------------------------
// Kernel B2: finalize ranks (64 blocks x 256). Each block scans the 64x8
// histogram (2KB, L2-hot) for its offsets + expert bases, then writes
// g_pos / scatter_indices / scores_sorted / counts.
// ---------------------------------------------------------------------------
__global__ void __launch_bounds__(SPB) rank_final_kernel(float* __restrict__ out)
{
    __shared__ int offE[E], totE[E], baseE[E];
    const int b = blockIdx.x;
    const int tid = threadIdx.x;

    if (tid < E) {
        int off = 0, tot = 0;
#pragma unroll
        for (int bb = 0; bb < NHB; bb++) {
            int h = g_bhist[bb * E + tid];
            if (bb < b) off += h;
            tot += h;
        }
        offE[tid] = off; totE[tid] = tot;
    }
    __syncthreads();
    if (tid == 0) {
        int s = 0;
#pragma unroll
        for (int e = 0; e < E; e++) { baseE[e] = s; s += totE[e]; }
    }
    __syncthreads();

    const int slot = b * SPB + tid;
    const int e = g_exp[slot];
    const int pos = baseE[e] + offE[e] + g_pos[slot];
    g_pos[slot] = pos;
    out[OFF_IDX + pos] = (float)(slot >> 1);   // scatter_indices
    out[OFF_SC  + pos] = g_prob[slot];         // scores_sorted

    if (b == 0 && tid < E) out[OFF_CNT + tid] = (float)totE[tid];
}

// ---------------------------------------------------------------------------
// Kernel C: scatter copy — read each token row once, write 2 destination rows.
// One block per token; 256 threads; loads before stores; streaming stores.
// ---------------------------------------------------------------------------
__global__ void __launch_bounds__(256) scatter_kernel(
    const float* __restrict__ x, float* __restrict__ out)
{
    const int t = blockIdx.x;
    const int p0 = g_pos[2 * t];
    const int p1 = g_pos[2 * t + 1];
    const float4* __restrict__ src = (const float4*)x + (size_t)t * 1024;
    float4* __restrict__ d0 = (float4*)(out + OFF_XG) + (size_t)p0 * 1024;
    float4* __restrict__ d1 = (float4*)(out + OFF_XG) + (size_t)p1 * 1024;

    const int i = threadIdx.x;
    float4 v0 = src[i];
    float4 v1 = src[i + 256];
    float4 v2 = src[i + 512];
    float4 v3 = src[i + 768];
    __stcs(d0 + i,       v0);
    __stcs(d0 + i + 256, v1);
    __stcs(d0 + i + 512, v2);
    __stcs(d0 + i + 768, v3);
    __stcs(d1 + i,       v0);
    __stcs(d1 + i + 256, v1);
    __stcs(d1 + i + 512, v2);
    __stcs(d1 + i + 768, v3);
}

extern "C" void kernel_launch(void* const* d_in, const int* in_sizes, int n_in,
                              void* d_out, int out_size)
{
    const float* x = (const float*)d_in[0];
    const float* W = (const float*)d_in[1];
    if (n_in >= 2 && in_sizes[0] == E * D && in_sizes[1] == (int)((size_t)T * D)) {
        const float* tmp = x; x = W; W = tmp;
    }
    float* out = (float*)d_out;

    router_scores_kernel<<<T / 32, 256>>>(x, W);
    rank_hist_kernel<<<NHB, SPB>>>();
    rank_final_kernel<<<NHB, SPB>>>(out);
    scatter_kernel<<<T, 256>>>(x, out);
}

// round 5
// speedup vs baseline: 2.9152x; 2.9152x over previous
#include <cuda_runtime.h>
#include <math.h>

#define T 8192
#define D 4096
#define E 8
#define KSEL 2
#define SLOTS (T * KSEL)
#define NHB 64             // hist blocks
#define SPB (SLOTS / NHB)  // 256 slots per hist block
#define RS2 1024           // ulonglong2 (16B) per D-row

// Output layout (float32, concatenated in reference-return order)
#define OFF_XG  0
#define OFF_CNT 67108864ll   // 16384*4096
#define OFF_IDX 67108872ll
#define OFF_SC  67125256ll

// Scratch (no allocations allowed -> __device__ globals)
__device__ int   g_exp[SLOTS];
__device__ float g_prob[SLOTS];
__device__ int   g_pos[SLOTS];
__device__ int   g_bhist[NHB * E];

// packed f32x2 fma: d = a*b + d  (2 fp32 FMAs in one instruction)
__device__ __forceinline__ void fma2(unsigned long long& d,
                                     unsigned long long a,
                                     unsigned long long b) {
    asm("fma.rn.f32x2 %0, %1, %2, %0;" : "+l"(d) : "l"(a), "l"(b));
}
__device__ __forceinline__ float unpack_add(unsigned long long v) {
    float lo, hi;
    asm("mov.b64 {%0, %1}, %2;" : "=f"(lo), "=f"(hi) : "l"(v));
    return lo + hi;
}

// ---------------------------------------------------------------------------
// Kernel A: router scores + top-2 + softmax.
// Warp handles 4 tokens over the FULL D (32 coalesced 128B iterations),
// so the shuffle-reduction tail is amortized over 64KB of x.
// f32x2 packed FMAs; x loads software-pipelined one iteration ahead.
// grid = T/16 blocks of 128 threads (4 warps, 16 tokens/block).
// ---------------------------------------------------------------------------
__global__ void __launch_bounds__(128) router_scores_kernel(
    const float* __restrict__ x, const float* __restrict__ W)
{
    const int warp = blockIdx.x * 4 + (threadIdx.x >> 5);
    const int lane = threadIdx.x & 31;
    const int t0   = warp * 4;

    const ulonglong2* __restrict__ xr0 =
        (const ulonglong2*)(x + (size_t)t0 * D);
    const ulonglong2* __restrict__ xr1 = xr0 + RS2;
    const ulonglong2* __restrict__ xr2 = xr0 + 2 * RS2;
    const ulonglong2* __restrict__ xr3 = xr0 + 3 * RS2;
    const ulonglong2* __restrict__ wr = (const ulonglong2*)W;

    unsigned long long acc[4][E];
#pragma unroll
    for (int j = 0; j < 4; j++)
#pragma unroll
        for (int e = 0; e < E; e++) acc[j][e] = 0ull;

    ulonglong2 xv0 = xr0[lane], xv1 = xr1[lane],
               xv2 = xr2[lane], xv3 = xr3[lane];

#pragma unroll 2
    for (int it = 0; it < 32; it++) {
        ulonglong2 nx0, nx1, nx2, nx3;
        if (it < 31) {
            const int ni = (it + 1) * 32 + lane;
            nx0 = xr0[ni]; nx1 = xr1[ni]; nx2 = xr2[ni]; nx3 = xr3[ni];
        }
        const int i = it * 32 + lane;
#pragma unroll
        for (int e = 0; e < E; e++) {
            ulonglong2 wv = wr[e * RS2 + i];
            fma2(acc[0][e], xv0.x, wv.x); fma2(acc[0][e], xv0.y, wv.y);
            fma2(acc[1][e], xv1.x, wv.x); fma2(acc[1][e], xv1.y, wv.y);
            fma2(acc[2][e], xv2.x, wv.x); fma2(acc[2][e], xv2.y, wv.y);
            fma2(acc[3][e], xv3.x, wv.x); fma2(acc[3][e], xv3.y, wv.y);
        }
        xv0 = nx0; xv1 = nx1; xv2 = nx2; xv3 = nx3;
    }

    // collapse packed halves, then warp tree-reduce 32 scalars
    float s[4][E];
#pragma unroll
    for (int j = 0; j < 4; j++)
#pragma unroll
        for (int e = 0; e < E; e++) s[j][e] = unpack_add(acc[j][e]);

#pragma unroll
    for (int off = 16; off > 0; off >>= 1) {
#pragma unroll
        for (int j = 0; j < 4; j++)
#pragma unroll
            for (int e = 0; e < E; e++)
                s[j][e] += __shfl_xor_sync(0xffffffffu, s[j][e], off);
    }

    // lanes 0..3 finalize token t0+lane (static indexing via predication)
#pragma unroll
    for (int j = 0; j < 4; j++) {
        if (lane == j) {
            const int t = t0 + j;
            float b0 = -3.4e38f, b1 = -3.4e38f;
            int i0 = 0, i1 = 0;
#pragma unroll
            for (int e = 0; e < E; e++) {
                float v = s[j][e];
                if (v > b0) { b1 = b0; i1 = i0; b0 = v; i0 = e; }
                else if (v > b1) { b1 = v; i1 = e; }
            }
            float ex = expf(b1 - b0);
            float inv = 1.f / (1.f + ex);
            ((int2*)g_exp)[t]    = make_int2(i0, i1);
            ((float2*)g_prob)[t] = make_float2(inv, ex * inv);
        }
    }
}

// ---------------------------------------------------------------------------
// Packed per-expert counters: 8 experts x 8-bit fields across two uints.
// ---------------------------------------------------------------------------
__device__ __forceinline__ void packAdd(int e, unsigned& lo, unsigned& hi) {
    if (e < 4) lo += 1u << (8 * e);
    else       hi += 1u << (8 * (e - 4));
}
__device__ __forceinline__ int fieldOf(unsigned lo, unsigned hi, int e) {
    unsigned v = (e < 4) ? lo : hi;
    return (int)((v >> (8 * (e & 3))) & 0xffu);
}

// ---------------------------------------------------------------------------
// Kernel B1: per-block histogram + stable local rank (64 blocks x 256).
// ---------------------------------------------------------------------------
__global__ void __launch_bounds__(SPB) rank_hist_kernel()
{
    __shared__ unsigned wlo[8], whi[8];
    const int tid  = threadIdx.x;
    const int wid  = tid >> 5;
    const int lane = tid & 31;
    const int slot = blockIdx.x * SPB + tid;

    const int e = g_exp[slot];
    unsigned lo = 0, hi = 0;
    packAdd(e, lo, hi);
    const unsigned mlo = lo, mhi = hi;

#pragma unroll
    for (int off = 1; off < 32; off <<= 1) {
        unsigned vlo = __shfl_up_sync(0xffffffffu, lo, off);
        unsigned vhi = __shfl_up_sync(0xffffffffu, hi, off);
        if (lane >= off) { lo += vlo; hi += vhi; }
    }
    if (lane == 31) { wlo[wid] = lo; whi[wid] = hi; }
    __syncthreads();

    unsigned plo = 0, phi = 0;
#pragma unroll
    for (int w2 = 0; w2 < 8; w2++)
        if (w2 < wid) { plo += wlo[w2]; phi += whi[w2]; }

    const unsigned exlo = plo + lo - mlo;
    const unsigned exhi = phi + hi - mhi;
    g_pos[slot] = fieldOf(exlo, exhi, e);   // local stable rank within block

    if (tid < E) {
        unsigned tlo = 0, thi = 0;
#pragma unroll
        for (int w2 = 0; w2 < 8; w2++) { tlo += wlo[w2]; thi += whi[w2]; }
        g_bhist[blockIdx.x * E + tid] = fieldOf(tlo, thi, tid);
    }
}

// ---------------------------------------------------------------------------
// Kernel B2: finalize ranks (64 blocks x 256).
// ---------------------------------------------------------------------------
__global__ void __launch_bounds__(SPB) rank_final_kernel(float* __restrict__ out)
{
    __shared__ int offE[E], totE[E], baseE[E];
    const int b = blockIdx.x;
    const int tid = threadIdx.x;

    if (tid < E) {
        int off = 0, tot = 0;
#pragma unroll
        for (int bb = 0; bb < NHB; bb++) {
            int h = g_bhist[bb * E + tid];
            if (bb < b) off += h;
            tot += h;
        }
        offE[tid] = off; totE[tid] = tot;
    }
    __syncthreads();
    if (tid == 0) {
        int s = 0;
#pragma unroll
        for (int e = 0; e < E; e++) { baseE[e] = s; s += totE[e]; }
    }
    __syncthreads();

    const int slot = b * SPB + tid;
    const int e = g_exp[slot];
    const int pos = baseE[e] + offE[e] + g_pos[slot];
    g_pos[slot] = pos;
    out[OFF_IDX + pos] = (float)(slot >> 1);   // scatter_indices
    out[OFF_SC  + pos] = g_prob[slot];         // scores_sorted

    if (b == 0 && tid < E) out[OFF_CNT + tid] = (float)totE[tid];
}

// ---------------------------------------------------------------------------
// Kernel C: scatter copy — read each token row once, write 2 destination rows.
// ---------------------------------------------------------------------------
__global__ void __launch_bounds__(256) scatter_kernel(
    const float* __restrict__ x, float* __restrict__ out)
{
    const int t = blockIdx.x;
    const int p0 = g_pos[2 * t];
    const int p1 = g_pos[2 * t + 1];
    const float4* __restrict__ src = (const float4*)x + (size_t)t * 1024;
    float4* __restrict__ d0 = (float4*)(out + OFF_XG) + (size_t)p0 * 1024;
    float4* __restrict__ d1 = (float4*)(out + OFF_XG) + (size_t)p1 * 1024;

    const int i = threadIdx.x;
    float4 v0 = src[i];
    float4 v1 = src[i + 256];
    float4 v2 = src[i + 512];
    float4 v3 = src[i + 768];
    __stcs(d0 + i,       v0);
    __stcs(d0 + i + 256, v1);
    __stcs(d0 + i + 512, v2);
    __stcs(d0 + i + 768, v3);
    __stcs(d1 + i,       v0);
    __stcs(d1 + i + 256, v1);
    __stcs(d1 + i + 512, v2);
    __stcs(d1 + i + 768, v3);
}

extern "C" void kernel_launch(void* const* d_in, const int* in_sizes, int n_in,
                              void* d_out, int out_size)
{
    const float* x = (const float*)d_in[0];
    const float* W = (const float*)d_in[1];
    if (n_in >= 2 && in_sizes[0] == E * D && in_sizes[1] == (int)((size_t)T * D)) {
        const float* tmp = x; x = W; W = tmp;
    }
    float* out = (float*)d_out;

    router_scores_kernel<<<T / 16, 128>>>(x, W);
    rank_hist_kernel<<<NHB, SPB>>>();
    rank_final_kernel<<<NHB, SPB>>>(out);
    scatter_kernel<<<T, 256>>>(x, out);
}

// round 6
// speedup vs baseline: 3.1770x; 1.0898x over previous
#include <cuda_runtime.h>
#include <math.h>

#define T 8192
#define D 4096
#define E 8
#define KSEL 2
#define SLOTS (T * KSEL)
#define NHB 64             // hist blocks
#define SPB (SLOTS / NHB)  // 256 slots per hist block

#define TB 32              // tokens per block (scores)
#define DC 512             // D-chunk (floats)
#define DC2 (DC / 8)       // ulonglong2 per expert-chunk-row = 64? no: DC/4 float4 =128 -> as ulonglong2 =128
// row stride in 16B units for D=4096: 1024

// Output layout (float32, concatenated in reference-return order)
#define OFF_XG  0
#define OFF_CNT 67108864ll   // 16384*4096
#define OFF_IDX 67108872ll
#define OFF_SC  67125256ll

// Scratch (no allocations allowed -> __device__ globals)
__device__ int   g_exp[SLOTS];
__device__ float g_prob[SLOTS];
__device__ int   g_pos[SLOTS];
__device__ int   g_bhist[NHB * E];

// packed f32x2 fma: d = a*b + d
__device__ __forceinline__ void fma2(unsigned long long& d,
                                     unsigned long long a,
                                     unsigned long long b) {
    asm("fma.rn.f32x2 %0, %1, %2, %0;" : "+l"(d) : "l"(a), "l"(b));
}
__device__ __forceinline__ float unpack_add(unsigned long long v) {
    float lo, hi;
    asm("mov.b64 {%0, %1}, %2;" : "=f"(lo), "=f"(hi) : "l"(v));
    return lo + hi;
}

// ---------------------------------------------------------------------------
// Kernel A: router scores + top-2 + softmax.
// Block = 256 threads (8 warps) x 32 tokens. D processed in 8 chunks of 512.
// Per chunk: 16KB W-chunk staged in SMEM by all threads (W leaves the L2
// path: 128KB per block total instead of 128KB per WARP), then each warp
// does 4 tokens x 4 coalesced 128B iterations with f32x2 FMAs, W via
// conflict-free LDS.128.
// ---------------------------------------------------------------------------
__global__ void __launch_bounds__(256) router_scores_kernel(
    const float* __restrict__ x, const float* __restrict__ W)
{
    __shared__ ulonglong2 Ws[E * 128];   // [e][i], i in 0..127 (16B units) = 16KB

    const int tid  = threadIdx.x;
    const int w    = tid >> 5;
    const int lane = tid & 31;
    const int t0   = blockIdx.x * TB + w * 4;

    const ulonglong2* __restrict__ x2 = (const ulonglong2*)x;
    const ulonglong2* __restrict__ w2 = (const ulonglong2*)W;
    const size_t xbase = (size_t)t0 * 1024;

    unsigned long long acc[4][E];
#pragma unroll
    for (int j = 0; j < 4; j++)
#pragma unroll
        for (int e = 0; e < E; e++) acc[j][e] = 0ull;

    for (int c = 0; c < D / DC; c++) {
        // stage W chunk: 1024 ulonglong2, 4 per thread
        __syncthreads();
#pragma unroll
        for (int k = 0; k < 4; k++) {
            const int idx = tid + k * 256;
            const int e = idx >> 7;
            const int i = idx & 127;
            Ws[idx] = w2[(size_t)e * 1024 + c * 128 + i];
        }
        __syncthreads();

#pragma unroll
        for (int it = 0; it < 4; it++) {
            const int i = it * 32 + lane;           // 0..127 within chunk
            const int gi = c * 128 + i;             // global 16B index in row
            ulonglong2 xv0 = x2[xbase + gi];
            ulonglong2 xv1 = x2[xbase + 1024 + gi];
            ulonglong2 xv2 = x2[xbase + 2048 + gi];
            ulonglong2 xv3 = x2[xbase + 3072 + gi];
#pragma unroll
            for (int e = 0; e < E; e++) {
                ulonglong2 wv = Ws[e * 128 + i];
                fma2(acc[0][e], xv0.x, wv.x); fma2(acc[0][e], xv0.y, wv.y);
                fma2(acc[1][e], xv1.x, wv.x); fma2(acc[1][e], xv1.y, wv.y);
                fma2(acc[2][e], xv2.x, wv.x); fma2(acc[2][e], xv2.y, wv.y);
                fma2(acc[3][e], xv3.x, wv.x); fma2(acc[3][e], xv3.y, wv.y);
            }
        }
    }

    // collapse packed halves, then warp tree-reduce 32 scalars
    float s[4][E];
#pragma unroll
    for (int j = 0; j < 4; j++)
#pragma unroll
        for (int e = 0; e < E; e++) s[j][e] = unpack_add(acc[j][e]);

#pragma unroll
    for (int off = 16; off > 0; off >>= 1) {
#pragma unroll
        for (int j = 0; j < 4; j++)
#pragma unroll
            for (int e = 0; e < E; e++)
                s[j][e] += __shfl_xor_sync(0xffffffffu, s[j][e], off);
    }

    // lanes 0..3 finalize token t0+lane
#pragma unroll
    for (int j = 0; j < 4; j++) {
        if (lane == j) {
            const int t = t0 + j;
            // stable top-2 (first occurrence wins ties, matching jax.lax.top_k)
            float b0 = -3.4e38f, b1 = -3.4e38f;
            int i0 = 0, i1 = 0;
#pragma unroll
            for (int e = 0; e < E; e++) {
                float v = s[j][e];
                if (v > b0) { b1 = b0; i1 = i0; b0 = v; i0 = e; }
                else if (v > b1) { b1 = v; i1 = e; }
            }
            float ex = expf(b1 - b0);
            float inv = 1.f / (1.f + ex);
            ((int2*)g_exp)[t]    = make_int2(i0, i1);
            ((float2*)g_prob)[t] = make_float2(inv, ex * inv);
        }
    }
}

// ---------------------------------------------------------------------------
// Packed per-expert counters: 8 experts x 8-bit fields across two uints.
// ---------------------------------------------------------------------------
__device__ __forceinline__ void packAdd(int e, unsigned& lo, unsigned& hi) {
    if (e < 4) lo += 1u << (8 * e);
    else       hi += 1u << (8 * (e - 4));
}
__device__ __forceinline__ int fieldOf(unsigned lo, unsigned hi, int e) {
    unsigned v = (e < 4) ? lo : hi;
    return (int)((v >> (8 * (e & 3))) & 0xffu);
}

// ---------------------------------------------------------------------------
// Kernel B1: per-block histogram + stable local rank (64 blocks x 256).
// ---------------------------------------------------------------------------
__global__ void __launch_bounds__(SPB) rank_hist_kernel()
{
    __shared__ unsigned wlo[8], whi[8];
    const int tid  = threadIdx.x;
    const int wid  = tid >> 5;
    const int lane = tid & 31;
    const int slot = blockIdx.x * SPB + tid;

    const int e = g_exp[slot];
    unsigned lo = 0, hi = 0;
    packAdd(e, lo, hi);
    const unsigned mlo = lo, mhi = hi;

#pragma unroll
    for (int off = 1; off < 32; off <<= 1) {
        unsigned vlo = __shfl_up_sync(0xffffffffu, lo, off);
        unsigned vhi = __shfl_up_sync(0xffffffffu, hi, off);
        if (lane >= off) { lo += vlo; hi += vhi; }
    }
    if (lane == 31) { wlo[wid] = lo; whi[wid] = hi; }
    __syncthreads();

    unsigned plo = 0, phi = 0;
#pragma unroll
    for (int w2 = 0; w2 < 8; w2++)
        if (w2 < wid) { plo += wlo[w2]; phi += whi[w2]; }

    const unsigned exlo = plo + lo - mlo;
    const unsigned exhi = phi + hi - mhi;
    g_pos[slot] = fieldOf(exlo, exhi, e);   // local stable rank within block

    if (tid < E) {
        unsigned tlo = 0, thi = 0;
#pragma unroll
        for (int w2 = 0; w2 < 8; w2++) { tlo += wlo[w2]; thi += whi[w2]; }
        g_bhist[blockIdx.x * E + tid] = fieldOf(tlo, thi, tid);
    }
}

// ---------------------------------------------------------------------------
// Kernel B2: finalize ranks (64 blocks x 256).
// ---------------------------------------------------------------------------
__global__ void __launch_bounds__(SPB) rank_final_kernel(float* __restrict__ out)
{
    __shared__ int offE[E], totE[E], baseE[E];
    const int b = blockIdx.x;
    const int tid = threadIdx.x;

    if (tid < E) {
        int off = 0, tot = 0;
#pragma unroll
        for (int bb = 0; bb < NHB; bb++) {
            int h = g_bhist[bb * E + tid];
            if (bb < b) off += h;
            tot += h;
        }
        offE[tid] = off; totE[tid] = tot;
    }
    __syncthreads();
    if (tid == 0) {
        int s = 0;
#pragma unroll
        for (int e = 0; e < E; e++) { baseE[e] = s; s += totE[e]; }
    }
    __syncthreads();

    const int slot = b * SPB + tid;
    const int e = g_exp[slot];
    const int pos = baseE[e] + offE[e] + g_pos[slot];
    g_pos[slot] = pos;
    out[OFF_IDX + pos] = (float)(slot >> 1);   // scatter_indices
    out[OFF_SC  + pos] = g_prob[slot];         // scores_sorted

    if (b == 0 && tid < E) out[OFF_CNT + tid] = (float)totE[tid];
}

// ---------------------------------------------------------------------------
// Kernel C: scatter copy — read each token row once, write 2 destination rows.
// ---------------------------------------------------------------------------
__global__ void __launch_bounds__(256) scatter_kernel(
    const float* __restrict__ x, float* __restrict__ out)
{
    const int t = blockIdx.x;
    const int p0 = g_pos[2 * t];
    const int p1 = g_pos[2 * t + 1];
    const float4* __restrict__ src = (const float4*)x + (size_t)t * 1024;
    float4* __restrict__ d0 = (float4*)(out + OFF_XG) + (size_t)p0 * 1024;
    float4* __restrict__ d1 = (float4*)(out + OFF_XG) + (size_t)p1 * 1024;

    const int i = threadIdx.x;
    float4 v0 = src[i];
    float4 v1 = src[i + 256];
    float4 v2 = src[i + 512];
    float4 v3 = src[i + 768];
    __stcs(d0 + i,       v0);
    __stcs(d0 + i + 256, v1);
    __stcs(d0 + i + 512, v2);
    __stcs(d0 + i + 768, v3);
    __stcs(d1 + i,       v0);
    __stcs(d1 + i + 256, v1);
    __stcs(d1 + i + 512, v2);
    __stcs(d1 + i + 768, v3);
}

extern "C" void kernel_launch(void* const* d_in, const int* in_sizes, int n_in,
                              void* d_out, int out_size)
{
    const float* x = (const float*)d_in[0];
    const float* W = (const float*)d_in[1];
    if (n_in >= 2 && in_sizes[0] == E * D && in_sizes[1] == (int)((size_t)T * D)) {
        const float* tmp = x; x = W; W = tmp;
    }
    float* out = (float*)d_out;

    router_scores_kernel<<<T / TB, 256>>>(x, W);
    rank_hist_kernel<<<NHB, SPB>>>();
    rank_final_kernel<<<NHB, SPB>>>(out);
    scatter_kernel<<<T, 256>>>(x, out);
}

// round 7
// speedup vs baseline: 3.7315x; 1.1745x over previous
#include <cuda_runtime.h>
#include <math.h>

#define T 8192
#define D 4096
#define E 8
#define KSEL 2
#define SLOTS (T * KSEL)
#define NHB 64             // hist blocks
#define SPB (SLOTS / NHB)  // 256 slots per hist block
#define RSU 1024           // ulonglong2 (16B) per D-row

// Output layout (float32, concatenated in reference-return order)
#define OFF_XG  0
#define OFF_CNT 67108864ll   // 16384*4096
#define OFF_IDX 67108872ll
#define OFF_SC  67125256ll

// Scratch (no allocations allowed -> __device__ globals)
__device__ int   g_exp[SLOTS];
__device__ float g_prob[SLOTS];
__device__ int   g_pos[SLOTS];
__device__ int   g_bhist[NHB * E];

// packed f32x2 fma: d = a*b + d
__device__ __forceinline__ void fma2(unsigned long long& d,
                                     unsigned long long a,
                                     unsigned long long b) {
    asm("fma.rn.f32x2 %0, %1, %2, %0;" : "+l"(d) : "l"(a), "l"(b));
}
__device__ __forceinline__ float unpack_add(unsigned long long v) {
    float lo, hi;
    asm("mov.b64 {%0, %1}, %2;" : "=f"(lo), "=f"(hi) : "l"(v));
    return lo + hi;
}

// ---------------------------------------------------------------------------
// Kernel A: router scores + top-2 + softmax.
// FULL W (128KB) staged once in dynamic SMEM -> barrier-free mainloop.
// 512 threads = 16 warps, 4 tokens/warp, 64 tokens/block, 128 blocks
// (exactly one wave, 1 block/SM). 32 coalesced 128B iterations over D,
// unroll x2, f32x2 packed FMAs, W via conflict-free LDS.128.
// ---------------------------------------------------------------------------
extern __shared__ ulonglong2 Ws[];   // [e * 1024 + i], 128KB

__global__ void __launch_bounds__(512) router_scores_kernel(
    const float* __restrict__ x, const float* __restrict__ W)
{
    const int tid  = threadIdx.x;
    const int w    = tid >> 5;
    const int lane = tid & 31;
    const int t0   = blockIdx.x * 64 + w * 4;

    const ulonglong2* __restrict__ x2 = (const ulonglong2*)x;
    const ulonglong2* __restrict__ w2 = (const ulonglong2*)W;

    // stage full W: 8192 ulonglong2, 16 per thread, coalesced
#pragma unroll
    for (int k = 0; k < 16; k++) {
        const int idx = tid + k * 512;
        Ws[idx] = w2[idx];
    }
    __syncthreads();

    const size_t xb = (size_t)t0 * RSU;
    unsigned long long acc[4][E];
#pragma unroll
    for (int j = 0; j < 4; j++)
#pragma unroll
        for (int e = 0; e < E; e++) acc[j][e] = 0ull;

#pragma unroll 2
    for (int it = 0; it < 32; it++) {
        const int i = it * 32 + lane;
        ulonglong2 xv0 = x2[xb + i];
        ulonglong2 xv1 = x2[xb + RSU + i];
        ulonglong2 xv2 = x2[xb + 2 * RSU + i];
        ulonglong2 xv3 = x2[xb + 3 * RSU + i];
#pragma unroll
        for (int e = 0; e < E; e++) {
            ulonglong2 wv = Ws[e * RSU + i];
            fma2(acc[0][e], xv0.x, wv.x); fma2(acc[0][e], xv0.y, wv.y);
            fma2(acc[1][e], xv1.x, wv.x); fma2(acc[1][e], xv1.y, wv.y);
            fma2(acc[2][e], xv2.x, wv.x); fma2(acc[2][e], xv2.y, wv.y);
            fma2(acc[3][e], xv3.x, wv.x); fma2(acc[3][e], xv3.y, wv.y);
        }
    }

    // collapse packed halves, then warp tree-reduce 32 scalars
    float s[4][E];
#pragma unroll
    for (int j = 0; j < 4; j++)
#pragma unroll
        for (int e = 0; e < E; e++) s[j][e] = unpack_add(acc[j][e]);

#pragma unroll
    for (int off = 16; off > 0; off >>= 1) {
#pragma unroll
        for (int j = 0; j < 4; j++)
#pragma unroll
            for (int e = 0; e < E; e++)
                s[j][e] += __shfl_xor_sync(0xffffffffu, s[j][e], off);
    }

    // lanes 0..3 finalize token t0+lane
#pragma unroll
    for (int j = 0; j < 4; j++) {
        if (lane == j) {
            const int t = t0 + j;
            // stable top-2 (first occurrence wins ties, matching jax.lax.top_k)
            float b0 = -3.4e38f, b1 = -3.4e38f;
            int i0 = 0, i1 = 0;
#pragma unroll
            for (int e = 0; e < E; e++) {
                float v = s[j][e];
                if (v > b0) { b1 = b0; i1 = i0; b0 = v; i0 = e; }
                else if (v > b1) { b1 = v; i1 = e; }
            }
            float ex = expf(b1 - b0);
            float inv = 1.f / (1.f + ex);
            ((int2*)g_exp)[t]    = make_int2(i0, i1);
            ((float2*)g_prob)[t] = make_float2(inv, ex * inv);
        }
    }
}

// ---------------------------------------------------------------------------
// Packed per-expert counters: 8 experts x 8-bit fields across two uints.
// ---------------------------------------------------------------------------
__device__ __forceinline__ void packAdd(int e, unsigned& lo, unsigned& hi) {
    if (e < 4) lo += 1u << (8 * e);
    else       hi += 1u << (8 * (e - 4));
}
__device__ __forceinline__ int fieldOf(unsigned lo, unsigned hi, int e) {
    unsigned v = (e < 4) ? lo : hi;
    return (int)((v >> (8 * (e & 3))) & 0xffu);
}

// ---------------------------------------------------------------------------
// Kernel B1: per-block histogram + stable local rank (64 blocks x 256).
// ---------------------------------------------------------------------------
__global__ void __launch_bounds__(SPB) rank_hist_kernel()
{
    __shared__ unsigned wlo[8], whi[8];
    const int tid  = threadIdx.x;
    const int wid  = tid >> 5;
    const int lane = tid & 31;
    const int slot = blockIdx.x * SPB + tid;

    const int e = g_exp[slot];
    unsigned lo = 0, hi = 0;
    packAdd(e, lo, hi);
    const unsigned mlo = lo, mhi = hi;

#pragma unroll
    for (int off = 1; off < 32; off <<= 1) {
        unsigned vlo = __shfl_up_sync(0xffffffffu, lo, off);
        unsigned vhi = __shfl_up_sync(0xffffffffu, hi, off);
        if (lane >= off) { lo += vlo; hi += vhi; }
    }
    if (lane == 31) { wlo[wid] = lo; whi[wid] = hi; }
    __syncthreads();

    unsigned plo = 0, phi = 0;
#pragma unroll
    for (int w2 = 0; w2 < 8; w2++)
        if (w2 < wid) { plo += wlo[w2]; phi += whi[w2]; }

    const unsigned exlo = plo + lo - mlo;
    const unsigned exhi = phi + hi - mhi;
    g_pos[slot] = fieldOf(exlo, exhi, e);   // local stable rank within block

    if (tid < E) {
        unsigned tlo = 0, thi = 0;
#pragma unroll
        for (int w2 = 0; w2 < 8; w2++) { tlo += wlo[w2]; thi += whi[w2]; }
        g_bhist[blockIdx.x * E + tid] = fieldOf(tlo, thi, tid);
    }
}

// ---------------------------------------------------------------------------
// Kernel B2: finalize ranks (64 blocks x 256).
// ---------------------------------------------------------------------------
__global__ void __launch_bounds__(SPB) rank_final_kernel(float* __restrict__ out)
{
    __shared__ int offE[E], totE[E], baseE[E];
    const int b = blockIdx.x;
    const int tid = threadIdx.x;

    if (tid < E) {
        int off = 0, tot = 0;
#pragma unroll
        for (int bb = 0; bb < NHB; bb++) {
            int h = g_bhist[bb * E + tid];
            if (bb < b) off += h;
            tot += h;
        }
        offE[tid] = off; totE[tid] = tot;
    }
    __syncthreads();
    if (tid == 0) {
        int s = 0;
#pragma unroll
        for (int e = 0; e < E; e++) { baseE[e] = s; s += totE[e]; }
    }
    __syncthreads();

    const int slot = b * SPB + tid;
    const int e = g_exp[slot];
    const int pos = baseE[e] + offE[e] + g_pos[slot];
    g_pos[slot] = pos;
    out[OFF_IDX + pos] = (float)(slot >> 1);   // scatter_indices
    out[OFF_SC  + pos] = g_prob[slot];         // scores_sorted

    if (b == 0 && tid < E) out[OFF_CNT + tid] = (float)totE[tid];
}

// ---------------------------------------------------------------------------
// Kernel C: scatter copy — read each token row once, write 2 destination rows.
// ---------------------------------------------------------------------------
__global__ void __launch_bounds__(256) scatter_kernel(
    const float* __restrict__ x, float* __restrict__ out)
{
    const int t = blockIdx.x;
    const int p0 = g_pos[2 * t];
    const int p1 = g_pos[2 * t + 1];
    const float4* __restrict__ src = (const float4*)x + (size_t)t * 1024;
    float4* __restrict__ d0 = (float4*)(out + OFF_XG) + (size_t)p0 * 1024;
    float4* __restrict__ d1 = (float4*)(out + OFF_XG) + (size_t)p1 * 1024;

    const int i = threadIdx.x;
    float4 v0 = src[i];
    float4 v1 = src[i + 256];
    float4 v2 = src[i + 512];
    float4 v3 = src[i + 768];
    __stcs(d0 + i,       v0);
    __stcs(d0 + i + 256, v1);
    __stcs(d0 + i + 512, v2);
    __stcs(d0 + i + 768, v3);
    __stcs(d1 + i,       v0);
    __stcs(d1 + i + 256, v1);
    __stcs(d1 + i + 512, v2);
    __stcs(d1 + i + 768, v3);
}

extern "C" void kernel_launch(void* const* d_in, const int* in_sizes, int n_in,
                              void* d_out, int out_size)
{
    const float* x = (const float*)d_in[0];
    const float* W = (const float*)d_in[1];
    if (n_in >= 2 && in_sizes[0] == E * D && in_sizes[1] == (int)((size_t)T * D)) {
        const float* tmp = x; x = W; W = tmp;
    }
    float* out = (float*)d_out;

    static int smem_set = 0;
    if (!smem_set) {
        cudaFuncSetAttribute(router_scores_kernel,
                             cudaFuncAttributeMaxDynamicSharedMemorySize,
                             E * D * (int)sizeof(float));
        smem_set = 1;
    }

    router_scores_kernel<<<T / 64, 512, E * D * sizeof(float)>>>(x, W);
    rank_hist_kernel<<<NHB, SPB>>>();
    rank_final_kernel<<<NHB, SPB>>>(out);
    scatter_kernel<<<T, 256>>>(x, out);
}